// round 13
// baseline (speedup 1.0000x reference)
#include <cuda_runtime.h>
#include <cuda_bf16.h>

typedef unsigned long long u64;
typedef unsigned int u32;

#define NROWS 16384
#define KCODES 8192
#define DDIM 256
#define CHUNK 128
#define NCHUNKS (KCODES / CHUNK)   // 64
#define NCTAS (NROWS / 128)        // 128
#define MARGIN 3.2e-4f             // >= worst-case bound 3.0e-4
#define SLICE 65536                // per-CTA candidate slice
#define CAND2_CAP (1 << 21)        // post-filter survivors
#define ROWB 528                   // 264 bf16 per padded smem row (bytes)

__device__ float g_c[NROWS];
__device__ float g_rowmax[NROWS];
__device__ u64 g_best[NROWS];
__device__ double g_loss;
__device__ u32 g_ccount[NCTAS];
__device__ u32 g_ncand2;
__device__ uint2 g_cand[NCTAS * SLICE];   // {key = row<<13|code, bf16-dot bits}
__device__ u32 g_cand2[CAND2_CAP];
__device__ uint2 g_cbb[KCODES * DDIM / 4];   // codebook as bf16 (4 MB)

// ---------------------------------------------------------------------------
__device__ __forceinline__ u32 smem_u32(const void* p) {
    u32 a;
    asm("{ .reg .u64 t; cvta.to.shared.u64 t, %1; cvt.u32.u64 %0, t; }"
        : "=r"(a) : "l"(p));
    return a;
}
__device__ __forceinline__ u32 f2bf2(float x, float y) {
    __nv_bfloat162 b = __float22bfloat162_rn(make_float2(x, y));
    return *reinterpret_cast<u32*>(&b);
}
__device__ __forceinline__ void ldsm_x4(u32 r[4], u32 addr) {
    asm volatile("ldmatrix.sync.aligned.m8n8.x4.shared.b16 {%0,%1,%2,%3}, [%4];"
        : "=r"(r[0]), "=r"(r[1]), "=r"(r[2]), "=r"(r[3]) : "r"(addr));
}
__device__ __forceinline__ void mma_bf16(float d[4], const u32 a[4],
                                         u32 b0, u32 b1) {
    asm volatile(
        "mma.sync.aligned.m16n8k16.row.col.f32.bf16.bf16.f32 "
        "{%0,%1,%2,%3}, {%4,%5,%6,%7}, {%8,%9}, {%0,%1,%2,%3};"
        : "+f"(d[0]), "+f"(d[1]), "+f"(d[2]), "+f"(d[3])
        : "r"(a[0]), "r"(a[1]), "r"(a[2]), "r"(a[3]), "r"(b0), "r"(b1));
}
__device__ __forceinline__ void cp16(u32 dst, const void* src) {
    asm volatile("cp.async.cg.shared.global [%0], [%1], 16;"
                 :: "r"(dst), "l"(src) : "memory");
}
#define CP_COMMIT() asm volatile("cp.async.commit_group;" ::: "memory")
#define CP_WAIT0()  asm volatile("cp.async.wait_group 0;" ::: "memory")

// monotone float<->u32 key
__device__ __forceinline__ u32 fkey(float f) {
    u32 b = __float_as_uint(f);
    return b ^ ((b & 0x80000000u) ? 0xFFFFFFFFu : 0x80000000u);
}
__device__ __forceinline__ float funkey(u32 k) {
    u32 b = (k & 0x80000000u) ? (k ^ 0x80000000u) : ~k;
    return __uint_as_float(b);
}

// ---------------------------------------------------------------------------
__global__ void k_cvt(const float* __restrict__ cb) {
    int i = blockIdx.x * 256 + threadIdx.x;
    float4 v = ((const float4*)cb)[i];
    g_cbb[i] = make_uint2(f2bf2(v.x, v.y), f2bf2(v.z, v.w));
}

__global__ void k_init(const float* __restrict__ z) {
    int row  = blockIdx.x * 8 + (threadIdx.x >> 5);
    int lane = threadIdx.x & 31;
    const float4* zp = (const float4*)(z + (size_t)row * DDIM);
    float4 a = zp[lane * 2];
    float4 b = zp[lane * 2 + 1];
    float s = a.x*a.x + a.y*a.y + a.z*a.z + a.w*a.w
            + b.x*b.x + b.y*b.y + b.z*b.z + b.w*b.w;
    #pragma unroll
    for (int o = 16; o > 0; o >>= 1) s += __shfl_xor_sync(0xffffffffu, s, o);
    if (lane == 0) {
        g_c[row] = s;
        g_best[row] = ~0ULL;
    }
    if (blockIdx.x == 0 && threadIdx.x == 0) {
        g_loss = 0.0; g_ncand2 = 0;
    }
}

// ---------------------------------------------------------------------------
// Phase 1: single GEMM pass. CTA = 128 rows x all codes, chunk = 128 codes.
// 512 threads = 16 warps as 4(row) x 4(code); warp tile 32 x 32.
// Accumulators double-buffered across chunk PAIRS: epilogue runs every 2
// chunks. Admission threshold is THREAD-LOCAL running max - MARGIN (provably
// a superset of the global-threshold set; the argmin's owning thread always
// admits it). Global per-row max reduced once at kernel end for k_filter.
// ---------------------------------------------------------------------------
__global__ void __launch_bounds__(512, 1)
k_phase1(const float* __restrict__ z) {
    extern __shared__ __align__(16) char sm[];
    u32 sbase = smem_u32(sm);
    u32* rmax = (u32*)(sm + 3 * 128 * ROWB);       // 128 u32 keys
    u32* s_cnt = (u32*)(sm + 3 * 128 * ROWB + 512);

    int tid = threadIdx.x;
    int lane = tid & 31;
    int wid = tid >> 5;
    int wr = wid >> 2;   // 0..3 : 32-row group
    int wc = wid & 3;    // 0..3 : 32-code group
    int rowBase = blockIdx.x * 128;
    uint2* my_slice = g_cand + (size_t)blockIdx.x * SLICE;

    if (tid < 128) rmax[tid] = 0u;
    if (tid == 0) *s_cnt = 0u;

    // ---- z tile [128 x 256] -> bf16 smem ----
    {
        const float4* src = (const float4*)(z + (size_t)rowBase * DDIM);
        #pragma unroll
        for (int t = 0; t < 16; t++) {
            int idx = tid + t * 512;
            int r = idx >> 6, c4 = idx & 63;
            float4 v = src[idx];
            *(uint2*)(sm + r * ROWB + c4 * 8) =
                make_uint2(f2bf2(v.x, v.y), f2bf2(v.z, v.w));
        }
    }

    // ---- codebook chunk 0 -> buffer 0 ----
    u32 buf_u32[2] = { sbase + 128u * ROWB, sbase + 2u * 128u * ROWB };
    {
        #pragma unroll
        for (int t = 0; t < 8; t++) {
            int idx = tid + t * 512;
            int r = idx >> 5, cc = idx & 31;
            cp16(buf_u32[0] + (u32)(r * ROWB + cc * 16),
                 &g_cbb[(size_t)r * 64 + cc * 2]);
        }
        CP_COMMIT();
    }
    CP_WAIT0();
    __syncthreads();

    u32 a_addr = sbase + (u32)((wr * 32 + (lane & 15)) * ROWB + (lane >> 4) * 16);
    u32 b_lane = (u32)((wc * 32 + (lane & 7) + ((lane >> 4) & 1) * 8) * ROWB
                       + ((lane >> 3) & 1) * 16);

    float runmax[2][2] = {{-1e30f, -1e30f}, {-1e30f, -1e30f}};
    float acc[2][2][4][4];   // [chunk parity][mi][nj][e]

    for (int c = 0; c < NCHUNKS; c++) {
        u32 cbuf = buf_u32[c & 1];
        bool pf = (c + 1 < NCHUNKS);
        int par = c & 1;

        if (pf) {
            u32 nb = buf_u32[(c + 1) & 1];
            const uint2* src = g_cbb + (size_t)(c + 1) * CHUNK * 64;
            #pragma unroll
            for (int t = 0; t < 8; t++) {
                int idx = tid + t * 512;
                int r = idx >> 5, cc = idx & 31;
                cp16(nb + (u32)(r * ROWB + cc * 16), src + (size_t)r * 64 + cc * 2);
            }
            CP_COMMIT();
        }

        #pragma unroll
        for (int mi = 0; mi < 2; mi++)
            #pragma unroll
            for (int nj = 0; nj < 4; nj++)
                #pragma unroll
                for (int e = 0; e < 4; e++)
                    acc[par][mi][nj][e] = 0.0f;

        #pragma unroll
        for (int kk = 0; kk < 16; kk++) {
            u32 a[2][4];
            ldsm_x4(a[0], a_addr + kk * 32);
            ldsm_x4(a[1], a_addr + 16 * ROWB + kk * 32);
            u32 b[2][4];
            ldsm_x4(b[0], cbuf + b_lane + kk * 32);
            ldsm_x4(b[1], cbuf + b_lane + 16 * ROWB + kk * 32);
            #pragma unroll
            for (int mi = 0; mi < 2; mi++)
                #pragma unroll
                for (int njp = 0; njp < 2; njp++) {
                    mma_bf16(acc[par][mi][njp * 2],     a[mi],
                             b[njp][0], b[njp][1]);
                    mma_bf16(acc[par][mi][njp * 2 + 1], a[mi],
                             b[njp][2], b[njp][3]);
                }
        }

        // ---- epilogue every 2 chunks: thread-local max + admission ----
        if (par == 1) {
            #pragma unroll
            for (int mi = 0; mi < 2; mi++) {
                #pragma unroll
                for (int h = 0; h < 2; h++) {
                    float m = runmax[mi][h];
                    #pragma unroll
                    for (int p = 0; p < 2; p++)
                        #pragma unroll
                        for (int nj = 0; nj < 4; nj++)
                            m = fmaxf(m, fmaxf(acc[p][mi][nj][h * 2],
                                               acc[p][mi][nj][h * 2 + 1]));
                    runmax[mi][h] = m;
                    float thr = m - MARGIN;

                    u32 msk = 0;
                    #pragma unroll
                    for (int p = 0; p < 2; p++)
                        #pragma unroll
                        for (int nj = 0; nj < 4; nj++) {
                            if (acc[p][mi][nj][h * 2] >= thr)
                                msk |= 1u << (p * 8 + nj * 2);
                            if (acc[p][mi][nj][h * 2 + 1] >= thr)
                                msk |= 1u << (p * 8 + nj * 2 + 1);
                        }
                    if (msk) {
                        u32 slot = atomicAdd(s_cnt, (u32)__popc(msk));
                        u32 row = (u32)(rowBase + wr * 32 + mi * 16 + h * 8
                                        + (lane >> 2));
                        #pragma unroll
                        for (int p = 0; p < 2; p++)
                            #pragma unroll
                            for (int nj = 0; nj < 4; nj++)
                                #pragma unroll
                                for (int e = 0; e < 2; e++) {
                                    if (msk & (1u << (p * 8 + nj * 2 + e))) {
                                        u32 code = (u32)((c - 1 + p) * CHUNK
                                                         + wc * 32 + nj * 8
                                                         + (lane & 3) * 2 + e);
                                        if (slot < SLICE)
                                            my_slice[slot] = make_uint2(
                                                (row << 13) | code,
                                                __float_as_uint(
                                                    acc[p][mi][nj][h * 2 + e]));
                                        slot++;
                                    }
                                }
                    }
                }
            }
        }

        if (pf) CP_WAIT0();
        __syncthreads();
    }

    // ---- per-row global max (once) + per-CTA candidate count ----
    #pragma unroll
    for (int mi = 0; mi < 2; mi++)
        #pragma unroll
        for (int h = 0; h < 2; h++) {
            float m = runmax[mi][h];
            m = fmaxf(m, __shfl_xor_sync(0xffffffffu, m, 1));
            m = fmaxf(m, __shfl_xor_sync(0xffffffffu, m, 2));
            if ((lane & 3) == 0)
                atomicMax(&rmax[wr * 32 + mi * 16 + h * 8 + (lane >> 2)],
                          fkey(m));
        }
    __syncthreads();
    if (tid < 128)
        g_rowmax[rowBase + tid] = funkey(rmax[tid]);
    if (tid == 0) {
        u32 n = *s_cnt;
        g_ccount[blockIdx.x] = n < SLICE ? n : SLICE;
    }
}

// ---------------------------------------------------------------------------
// Filter: one block per CTA slice; keep dot >= rowmax_final - MARGIN.
// ---------------------------------------------------------------------------
__global__ void k_filter() {
    u32 b = blockIdx.x;
    u32 n = g_ccount[b];
    const uint2* slice = g_cand + (size_t)b * SLICE;
    u32 lane = threadIdx.x & 31;
    for (u32 ib = threadIdx.x & ~31u; ib < n; ib += blockDim.x) {
        u32 i = ib + lane;
        bool keep = false;
        u32 key = 0;
        if (i < n) {
            uint2 cd = slice[i];
            key = cd.x;
            keep = __uint_as_float(cd.y) >= g_rowmax[key >> 13] - MARGIN;
        }
        u32 mask = __ballot_sync(0xffffffffu, keep);
        if (mask) {
            int leader = __ffs(mask) - 1;
            u32 base = 0;
            if ((int)lane == leader)
                base = atomicAdd(&g_ncand2, (u32)__popc(mask));
            base = __shfl_sync(0xffffffffu, base, leader);
            if (keep) {
                u32 slot = base + (u32)__popc(mask & ((1u << lane) - 1u));
                if (slot < CAND2_CAP) g_cand2[slot] = key;
            }
        }
    }
}

// ---------------------------------------------------------------------------
// Rescore: exact fp32, bit-identical to the proven Round-2 math.
// ---------------------------------------------------------------------------
__global__ void k_rescore(const float* __restrict__ z, const float* __restrict__ cb) {
    u32 n = g_ncand2;
    if (n > CAND2_CAP) n = CAND2_CAP;
    for (u32 i = blockIdx.x * blockDim.x + threadIdx.x; i < n;
         i += gridDim.x * blockDim.x) {
        u32 rc = g_cand2[i];
        u32 row = rc >> 13;
        u32 code = rc & 8191u;
        const float4* zr = (const float4*)(z + (size_t)row * DDIM);
        const float4* wr = (const float4*)(cb + (size_t)code * DDIM);
        float dot = 0.0f;
        #pragma unroll 8
        for (int q = 0; q < DDIM / 4; q++) {
            float4 a = zr[q];
            float4 b = wr[q];
            dot = __fmaf_rn(a.x, b.x, dot);
            dot = __fmaf_rn(a.y, b.y, dot);
            dot = __fmaf_rn(a.z, b.z, dot);
            dot = __fmaf_rn(a.w, b.w, dot);
        }
        float t = __fmaf_rn(-2.0f, dot, g_c[row]);
        u64 p = ((u64)__float_as_uint(t) << 32) | code;
        atomicMin(&g_best[row], p);
    }
}

// ---------------------------------------------------------------------------
__global__ void k_out(const float* __restrict__ z, const float* __restrict__ cb,
                      float* __restrict__ out) {
    __shared__ double sred[8];
    int wid = threadIdx.x >> 5;
    int lane = threadIdx.x & 31;
    int n = blockIdx.x * 8 + wid;
    u32 idx = (u32)(g_best[n] & 0xffffffffu);
    const float4* zr = (const float4*)(z + (size_t)n * DDIM);
    const float4* qr = (const float4*)(cb + (size_t)idx * DDIM);
    float4* orow = (float4*)(out + (size_t)n * DDIM);
    double s = 0.0;
    #pragma unroll
    for (int t = 0; t < 2; t++) {
        float4 zv = zr[lane + t * 32];
        float4 qv = qr[lane + t * 32];
        float4 ov;
        ov.x = zv.x + (qv.x - zv.x);
        ov.y = zv.y + (qv.y - zv.y);
        ov.z = zv.z + (qv.z - zv.z);
        ov.w = zv.w + (qv.w - zv.w);
        orow[lane + t * 32] = ov;
        float dx = zv.x - qv.x, dy = zv.y - qv.y;
        float dz = zv.z - qv.z, dw = zv.w - qv.w;
        s += (double)(dx * dx) + (double)(dy * dy)
           + (double)(dz * dz) + (double)(dw * dw);
    }
    #pragma unroll
    for (int o = 16; o > 0; o >>= 1) s += __shfl_xor_sync(0xffffffffu, s, o);
    if (lane == 0) {
        sred[wid] = s;
        out[(size_t)NROWS * DDIM + 1 + n] = (float)idx;
    }
    __syncthreads();
    if (threadIdx.x == 0) {
        double t = 0.0;
        #pragma unroll
        for (int i = 0; i < 8; i++) t += sred[i];
        atomicAdd(&g_loss, t);
    }
}

__global__ void k_loss(float* __restrict__ out) {
    float m = (float)(g_loss / (double)((size_t)NROWS * DDIM));
    out[(size_t)NROWS * DDIM] = m + 0.25f * m;
}

// ---------------------------------------------------------------------------
extern "C" void kernel_launch(void* const* d_in, const int* in_sizes, int n_in,
                              void* d_out, int out_size) {
    const float* z  = (const float*)d_in[0];
    const float* cb = (const float*)d_in[1];
    if (n_in >= 2 && in_sizes[0] == KCODES * DDIM && in_sizes[1] == NROWS * DDIM) {
        z  = (const float*)d_in[1];
        cb = (const float*)d_in[0];
    }
    float* out = (float*)d_out;
    (void)out_size;

    const int smem_bytes = 3 * 128 * ROWB + 512 + 16;   // tiles + rmax + cnt
    static int attr_done = 0;
    if (!attr_done) {
        cudaFuncSetAttribute(k_phase1, cudaFuncAttributeMaxDynamicSharedMemorySize,
                             smem_bytes);
        attr_done = 1;
    }

    k_cvt<<<KCODES * DDIM / 4 / 256, 256>>>(cb);
    k_init<<<NROWS / 8, 256>>>(z);
    k_phase1<<<NCTAS, 512, smem_bytes>>>(z);
    k_filter<<<NCTAS, 1024>>>();
    k_rescore<<<512, 256>>>(z, cb);
    k_out<<<NROWS / 8, 256>>>(z, cb, out);
    k_loss<<<1, 1>>>(out);
}

// round 14
// speedup vs baseline: 1.2659x; 1.2659x over previous
#include <cuda_runtime.h>
#include <cuda_bf16.h>

typedef unsigned long long u64;
typedef unsigned int u32;

#define NROWS 16384
#define KCODES 8192
#define DDIM 256
#define CHUNK 128
#define NCHUNKS (KCODES / CHUNK)   // 64
#define NCTAS (NROWS / 128)        // 128
#define MARGIN 3.2e-4f             // >= worst-case bound 3.0e-4
#define WSLICE 4096                // per-warp candidate slice
#define NWARPS 16
#define SLICE (WSLICE * NWARPS)    // per-CTA slice (65536)
#define CAND2_CAP (1 << 21)        // post-filter survivors
#define ROWB 528                   // 264 bf16 per padded smem row (bytes)

__device__ float g_c[NROWS];
__device__ float g_rowmax[NROWS];
__device__ u64 g_best[NROWS];
__device__ double g_loss;
__device__ u32 g_ccount[NCTAS * NWARPS];
__device__ u32 g_ncand2;
__device__ uint2 g_cand[NCTAS * SLICE];   // {key = row<<13|code, bf16-dot bits}
__device__ u32 g_cand2[CAND2_CAP];
__device__ uint2 g_cbb[KCODES * DDIM / 4];   // codebook as bf16 (4 MB)

// ---------------------------------------------------------------------------
__device__ __forceinline__ u32 smem_u32(const void* p) {
    u32 a;
    asm("{ .reg .u64 t; cvta.to.shared.u64 t, %1; cvt.u32.u64 %0, t; }"
        : "=r"(a) : "l"(p));
    return a;
}
__device__ __forceinline__ u32 f2bf2(float x, float y) {
    __nv_bfloat162 b = __float22bfloat162_rn(make_float2(x, y));
    return *reinterpret_cast<u32*>(&b);
}
__device__ __forceinline__ void ldsm_x4(u32 r[4], u32 addr) {
    asm volatile("ldmatrix.sync.aligned.m8n8.x4.shared.b16 {%0,%1,%2,%3}, [%4];"
        : "=r"(r[0]), "=r"(r[1]), "=r"(r[2]), "=r"(r[3]) : "r"(addr));
}
__device__ __forceinline__ void mma_bf16(float d[4], const u32 a[4],
                                         u32 b0, u32 b1) {
    asm volatile(
        "mma.sync.aligned.m16n8k16.row.col.f32.bf16.bf16.f32 "
        "{%0,%1,%2,%3}, {%4,%5,%6,%7}, {%8,%9}, {%0,%1,%2,%3};"
        : "+f"(d[0]), "+f"(d[1]), "+f"(d[2]), "+f"(d[3])
        : "r"(a[0]), "r"(a[1]), "r"(a[2]), "r"(a[3]), "r"(b0), "r"(b1));
}
__device__ __forceinline__ void cp16(u32 dst, const void* src) {
    asm volatile("cp.async.cg.shared.global [%0], [%1], 16;"
                 :: "r"(dst), "l"(src) : "memory");
}
#define CP_COMMIT() asm volatile("cp.async.commit_group;" ::: "memory")
#define CP_WAIT0()  asm volatile("cp.async.wait_group 0;" ::: "memory")

// monotone float<->u32 key
__device__ __forceinline__ u32 fkey(float f) {
    u32 b = __float_as_uint(f);
    return b ^ ((b & 0x80000000u) ? 0xFFFFFFFFu : 0x80000000u);
}
__device__ __forceinline__ float funkey(u32 k) {
    u32 b = (k & 0x80000000u) ? (k ^ 0x80000000u) : ~k;
    return __uint_as_float(b);
}

// ---------------------------------------------------------------------------
__global__ void k_cvt(const float* __restrict__ cb) {
    int i = blockIdx.x * 256 + threadIdx.x;
    float4 v = ((const float4*)cb)[i];
    g_cbb[i] = make_uint2(f2bf2(v.x, v.y), f2bf2(v.z, v.w));
}

__global__ void k_init(const float* __restrict__ z) {
    int row  = blockIdx.x * 8 + (threadIdx.x >> 5);
    int lane = threadIdx.x & 31;
    const float4* zp = (const float4*)(z + (size_t)row * DDIM);
    float4 a = zp[lane * 2];
    float4 b = zp[lane * 2 + 1];
    float s = a.x*a.x + a.y*a.y + a.z*a.z + a.w*a.w
            + b.x*b.x + b.y*b.y + b.z*b.z + b.w*b.w;
    #pragma unroll
    for (int o = 16; o > 0; o >>= 1) s += __shfl_xor_sync(0xffffffffu, s, o);
    if (lane == 0) {
        g_c[row] = s;
        g_best[row] = ~0ULL;
    }
    if (blockIdx.x == 0 && threadIdx.x == 0) {
        g_loss = 0.0; g_ncand2 = 0;
    }
}

// ---------------------------------------------------------------------------
// Phase 1: single GEMM pass. CTA = 128 rows x all codes, chunk = 128 codes.
// 512 threads = 16 warps as 4(row) x 4(code); warp tile 32 x 32.
// Admission: per-WARP smem counter (16 counters in distinct banks -> no
// cross-warp atomic serialization) + per-warp g_cand sub-slice. Candidate
// set is deterministic; downstream filter/rescore are order-independent.
// ---------------------------------------------------------------------------
__global__ void __launch_bounds__(512, 1)
k_phase1(const float* __restrict__ z) {
    extern __shared__ __align__(16) char sm[];
    u32 sbase = smem_u32(sm);
    u32* rmax  = (u32*)(sm + 3 * 128 * ROWB);        // 128 u32 keys
    u32* s_cnt = (u32*)(sm + 3 * 128 * ROWB + 512);  // 16 per-warp counters

    int tid = threadIdx.x;
    int lane = tid & 31;
    int wid = tid >> 5;
    int wr = wid >> 2;   // 0..3 : 32-row group
    int wc = wid & 3;    // 0..3 : 32-code group
    int rowBase = blockIdx.x * 128;
    uint2* my_slice = g_cand + (size_t)blockIdx.x * SLICE + (size_t)wid * WSLICE;

    if (tid < 128) rmax[tid] = 0u;
    if (tid < NWARPS) s_cnt[tid] = 0u;

    // ---- z tile [128 x 256] -> bf16 smem ----
    {
        const float4* src = (const float4*)(z + (size_t)rowBase * DDIM);
        #pragma unroll
        for (int t = 0; t < 16; t++) {
            int idx = tid + t * 512;
            int r = idx >> 6, c4 = idx & 63;
            float4 v = src[idx];
            *(uint2*)(sm + r * ROWB + c4 * 8) =
                make_uint2(f2bf2(v.x, v.y), f2bf2(v.z, v.w));
        }
    }

    // ---- codebook chunk 0 -> buffer 0 ----
    u32 buf_u32[2] = { sbase + 128u * ROWB, sbase + 2u * 128u * ROWB };
    {
        #pragma unroll
        for (int t = 0; t < 8; t++) {
            int idx = tid + t * 512;
            int r = idx >> 5, cc = idx & 31;
            cp16(buf_u32[0] + (u32)(r * ROWB + cc * 16),
                 &g_cbb[(size_t)r * 64 + cc * 2]);
        }
        CP_COMMIT();
    }
    CP_WAIT0();
    __syncthreads();

    u32 a_addr = sbase + (u32)((wr * 32 + (lane & 15)) * ROWB + (lane >> 4) * 16);
    u32 b_lane = (u32)((wc * 32 + (lane & 7) + ((lane >> 4) & 1) * 8) * ROWB
                       + ((lane >> 3) & 1) * 16);

    float runmax[2][2] = {{-1e30f, -1e30f}, {-1e30f, -1e30f}};

    for (int c = 0; c < NCHUNKS; c++) {
        u32 cbuf = buf_u32[c & 1];
        bool pf = (c + 1 < NCHUNKS);

        if (pf) {
            u32 nb = buf_u32[(c + 1) & 1];
            const uint2* src = g_cbb + (size_t)(c + 1) * CHUNK * 64;
            #pragma unroll
            for (int t = 0; t < 8; t++) {
                int idx = tid + t * 512;
                int r = idx >> 5, cc = idx & 31;
                cp16(nb + (u32)(r * ROWB + cc * 16), src + (size_t)r * 64 + cc * 2);
            }
            CP_COMMIT();
        }

        float acc[2][4][4];
        #pragma unroll
        for (int mi = 0; mi < 2; mi++)
            #pragma unroll
            for (int nj = 0; nj < 4; nj++)
                #pragma unroll
                for (int e = 0; e < 4; e++)
                    acc[mi][nj][e] = 0.0f;

        #pragma unroll
        for (int kk = 0; kk < 16; kk++) {
            u32 a[2][4];
            ldsm_x4(a[0], a_addr + kk * 32);
            ldsm_x4(a[1], a_addr + 16 * ROWB + kk * 32);
            u32 b[2][4];
            ldsm_x4(b[0], cbuf + b_lane + kk * 32);
            ldsm_x4(b[1], cbuf + b_lane + 16 * ROWB + kk * 32);
            #pragma unroll
            for (int mi = 0; mi < 2; mi++)
                #pragma unroll
                for (int njp = 0; njp < 2; njp++) {
                    mma_bf16(acc[mi][njp * 2],     a[mi], b[njp][0], b[njp][1]);
                    mma_bf16(acc[mi][njp * 2 + 1], a[mi], b[njp][2], b[njp][3]);
                }
        }

        // ---- epilogue: chunk max -> runmax -> per-warp-counter admission ----
        #pragma unroll
        for (int mi = 0; mi < 2; mi++) {
            #pragma unroll
            for (int h = 0; h < 2; h++) {
                float m = -1e30f;
                #pragma unroll
                for (int nj = 0; nj < 4; nj++)
                    m = fmaxf(m, fmaxf(acc[mi][nj][h * 2], acc[mi][nj][h * 2 + 1]));
                m = fmaxf(m, __shfl_xor_sync(0xffffffffu, m, 1));
                m = fmaxf(m, __shfl_xor_sync(0xffffffffu, m, 2));
                runmax[mi][h] = fmaxf(runmax[mi][h], m);
                float thr = runmax[mi][h] - MARGIN;

                u32 msk = 0;
                #pragma unroll
                for (int nj = 0; nj < 4; nj++) {
                    if (acc[mi][nj][h * 2]     >= thr) msk |= 1u << (nj * 2);
                    if (acc[mi][nj][h * 2 + 1] >= thr) msk |= 1u << (nj * 2 + 1);
                }
                if (msk) {
                    u32 slot = atomicAdd(&s_cnt[wid], (u32)__popc(msk));
                    u32 row = (u32)(rowBase + wr * 32 + mi * 16 + h * 8
                                    + (lane >> 2));
                    #pragma unroll
                    for (int nj = 0; nj < 4; nj++) {
                        #pragma unroll
                        for (int e = 0; e < 2; e++) {
                            if (msk & (1u << (nj * 2 + e))) {
                                u32 code = (u32)(c * CHUNK + wc * 32 + nj * 8
                                                 + (lane & 3) * 2 + e);
                                if (slot < WSLICE)
                                    my_slice[slot] = make_uint2(
                                        (row << 13) | code,
                                        __float_as_uint(acc[mi][nj][h * 2 + e]));
                                slot++;
                            }
                        }
                    }
                }
            }
        }

        if (pf) CP_WAIT0();
        __syncthreads();
    }

    // ---- per-row global max + per-warp candidate counts ----
    #pragma unroll
    for (int mi = 0; mi < 2; mi++)
        #pragma unroll
        for (int h = 0; h < 2; h++)
            if ((lane & 3) == 0)
                atomicMax(&rmax[wr * 32 + mi * 16 + h * 8 + (lane >> 2)],
                          fkey(runmax[mi][h]));
    __syncthreads();
    if (tid < 128)
        g_rowmax[rowBase + tid] = funkey(rmax[tid]);
    if (tid < NWARPS) {
        u32 n = s_cnt[tid];
        g_ccount[blockIdx.x * NWARPS + tid] = n < WSLICE ? n : WSLICE;
    }
}

// ---------------------------------------------------------------------------
// Filter: one block per warp-slice; keep dot >= rowmax_final - MARGIN.
// ---------------------------------------------------------------------------
__global__ void k_filter() {
    u32 bs = blockIdx.x;                 // [0, NCTAS*NWARPS)
    u32 n = g_ccount[bs];
    const uint2* slice = g_cand + (size_t)(bs >> 4) * SLICE
                               + (size_t)(bs & 15) * WSLICE;
    u32 lane = threadIdx.x & 31;
    for (u32 ib = threadIdx.x & ~31u; ib < n; ib += blockDim.x) {
        u32 i = ib + lane;
        bool keep = false;
        u32 key = 0;
        if (i < n) {
            uint2 cd = slice[i];
            key = cd.x;
            keep = __uint_as_float(cd.y) >= g_rowmax[key >> 13] - MARGIN;
        }
        u32 mask = __ballot_sync(0xffffffffu, keep);
        if (mask) {
            int leader = __ffs(mask) - 1;
            u32 base = 0;
            if ((int)lane == leader)
                base = atomicAdd(&g_ncand2, (u32)__popc(mask));
            base = __shfl_sync(0xffffffffu, base, leader);
            if (keep) {
                u32 slot = base + (u32)__popc(mask & ((1u << lane) - 1u));
                if (slot < CAND2_CAP) g_cand2[slot] = key;
            }
        }
    }
}

// ---------------------------------------------------------------------------
// Rescore: exact fp32, bit-identical to the proven Round-2 math.
// ---------------------------------------------------------------------------
__global__ void k_rescore(const float* __restrict__ z, const float* __restrict__ cb) {
    u32 n = g_ncand2;
    if (n > CAND2_CAP) n = CAND2_CAP;
    for (u32 i = blockIdx.x * blockDim.x + threadIdx.x; i < n;
         i += gridDim.x * blockDim.x) {
        u32 rc = g_cand2[i];
        u32 row = rc >> 13;
        u32 code = rc & 8191u;
        const float4* zr = (const float4*)(z + (size_t)row * DDIM);
        const float4* wr = (const float4*)(cb + (size_t)code * DDIM);
        float dot = 0.0f;
        #pragma unroll 8
        for (int q = 0; q < DDIM / 4; q++) {
            float4 a = zr[q];
            float4 b = wr[q];
            dot = __fmaf_rn(a.x, b.x, dot);
            dot = __fmaf_rn(a.y, b.y, dot);
            dot = __fmaf_rn(a.z, b.z, dot);
            dot = __fmaf_rn(a.w, b.w, dot);
        }
        float t = __fmaf_rn(-2.0f, dot, g_c[row]);
        u64 p = ((u64)__float_as_uint(t) << 32) | code;
        atomicMin(&g_best[row], p);
    }
}

// ---------------------------------------------------------------------------
__global__ void k_out(const float* __restrict__ z, const float* __restrict__ cb,
                      float* __restrict__ out) {
    __shared__ double sred[8];
    int wid = threadIdx.x >> 5;
    int lane = threadIdx.x & 31;
    int n = blockIdx.x * 8 + wid;
    u32 idx = (u32)(g_best[n] & 0xffffffffu);
    const float4* zr = (const float4*)(z + (size_t)n * DDIM);
    const float4* qr = (const float4*)(cb + (size_t)idx * DDIM);
    float4* orow = (float4*)(out + (size_t)n * DDIM);
    double s = 0.0;
    #pragma unroll
    for (int t = 0; t < 2; t++) {
        float4 zv = zr[lane + t * 32];
        float4 qv = qr[lane + t * 32];
        float4 ov;
        ov.x = zv.x + (qv.x - zv.x);
        ov.y = zv.y + (qv.y - zv.y);
        ov.z = zv.z + (qv.z - zv.z);
        ov.w = zv.w + (qv.w - zv.w);
        orow[lane + t * 32] = ov;
        float dx = zv.x - qv.x, dy = zv.y - qv.y;
        float dz = zv.z - qv.z, dw = zv.w - qv.w;
        s += (double)(dx * dx) + (double)(dy * dy)
           + (double)(dz * dz) + (double)(dw * dw);
    }
    #pragma unroll
    for (int o = 16; o > 0; o >>= 1) s += __shfl_xor_sync(0xffffffffu, s, o);
    if (lane == 0) {
        sred[wid] = s;
        out[(size_t)NROWS * DDIM + 1 + n] = (float)idx;
    }
    __syncthreads();
    if (threadIdx.x == 0) {
        double t = 0.0;
        #pragma unroll
        for (int i = 0; i < 8; i++) t += sred[i];
        atomicAdd(&g_loss, t);
    }
}

__global__ void k_loss(float* __restrict__ out) {
    float m = (float)(g_loss / (double)((size_t)NROWS * DDIM));
    out[(size_t)NROWS * DDIM] = m + 0.25f * m;
}

// ---------------------------------------------------------------------------
extern "C" void kernel_launch(void* const* d_in, const int* in_sizes, int n_in,
                              void* d_out, int out_size) {
    const float* z  = (const float*)d_in[0];
    const float* cb = (const float*)d_in[1];
    if (n_in >= 2 && in_sizes[0] == KCODES * DDIM && in_sizes[1] == NROWS * DDIM) {
        z  = (const float*)d_in[1];
        cb = (const float*)d_in[0];
    }
    float* out = (float*)d_out;
    (void)out_size;

    const int smem_bytes = 3 * 128 * ROWB + 512 + 64;   // tiles + rmax + cnts
    static int attr_done = 0;
    if (!attr_done) {
        cudaFuncSetAttribute(k_phase1, cudaFuncAttributeMaxDynamicSharedMemorySize,
                             smem_bytes);
        attr_done = 1;
    }

    k_cvt<<<KCODES * DDIM / 4 / 256, 256>>>(cb);
    k_init<<<NROWS / 8, 256>>>(z);
    k_phase1<<<NCTAS, 512, smem_bytes>>>(z);
    k_filter<<<NCTAS * NWARPS, 256>>>();
    k_rescore<<<512, 256>>>(z, cb);
    k_out<<<NROWS / 8, 256>>>(z, cb, out);
    k_loss<<<1, 1>>>(out);
}

// round 15
// speedup vs baseline: 1.3285x; 1.0495x over previous
#include <cuda_runtime.h>
#include <cuda_bf16.h>

typedef unsigned long long u64;
typedef unsigned int u32;

#define NROWS 16384
#define KCODES 8192
#define DDIM 256
#define CHUNK 128
#define NCHUNKS (KCODES / CHUNK)   // 64
#define NTILES (NROWS / 128)       // 128
#define NUNITS (NTILES * NCHUNKS)  // 8192 work units
#define GRID1 148                  // persistent CTAs (one per SM)
#define MARGIN 3.2e-4f             // >= worst-case bound 3.0e-4
#define WSLICE 4096                // per-warp candidate slice
#define NWARPS 16
#define ROWB 528                   // 264 bf16 per padded smem row (bytes)

__device__ float g_c[NROWS];
__device__ u32 g_rowmaxk[NROWS];   // monotone fkey of per-row max bf16 dot
__device__ u64 g_best[NROWS];
__device__ double g_loss;
__device__ u32 g_ccount[GRID1 * NWARPS];
__device__ u32 g_done;
__device__ uint2 g_cand[(size_t)GRID1 * NWARPS * WSLICE];
__device__ uint2 g_cbb[KCODES * DDIM / 4];   // codebook as bf16 (4 MB)

// ---------------------------------------------------------------------------
__device__ __forceinline__ u32 smem_u32(const void* p) {
    u32 a;
    asm("{ .reg .u64 t; cvta.to.shared.u64 t, %1; cvt.u32.u64 %0, t; }"
        : "=r"(a) : "l"(p));
    return a;
}
__device__ __forceinline__ u32 f2bf2(float x, float y) {
    __nv_bfloat162 b = __float22bfloat162_rn(make_float2(x, y));
    return *reinterpret_cast<u32*>(&b);
}
__device__ __forceinline__ void ldsm_x4(u32 r[4], u32 addr) {
    asm volatile("ldmatrix.sync.aligned.m8n8.x4.shared.b16 {%0,%1,%2,%3}, [%4];"
        : "=r"(r[0]), "=r"(r[1]), "=r"(r[2]), "=r"(r[3]) : "r"(addr));
}
__device__ __forceinline__ void mma_bf16(float d[4], const u32 a[4],
                                         u32 b0, u32 b1) {
    asm volatile(
        "mma.sync.aligned.m16n8k16.row.col.f32.bf16.bf16.f32 "
        "{%0,%1,%2,%3}, {%4,%5,%6,%7}, {%8,%9}, {%0,%1,%2,%3};"
        : "+f"(d[0]), "+f"(d[1]), "+f"(d[2]), "+f"(d[3])
        : "r"(a[0]), "r"(a[1]), "r"(a[2]), "r"(a[3]), "r"(b0), "r"(b1));
}
__device__ __forceinline__ void cp16(u32 dst, const void* src) {
    asm volatile("cp.async.cg.shared.global [%0], [%1], 16;"
                 :: "r"(dst), "l"(src) : "memory");
}
#define CP_COMMIT() asm volatile("cp.async.commit_group;" ::: "memory")
#define CP_WAIT0()  asm volatile("cp.async.wait_group 0;" ::: "memory")

// monotone float<->u32 key
__device__ __forceinline__ u32 fkey(float f) {
    u32 b = __float_as_uint(f);
    return b ^ ((b & 0x80000000u) ? 0xFFFFFFFFu : 0x80000000u);
}
__device__ __forceinline__ float funkey(u32 k) {
    u32 b = (k & 0x80000000u) ? (k ^ 0x80000000u) : ~k;
    return __uint_as_float(b);
}

// ---------------------------------------------------------------------------
// k_prep: fused init (|z|^2, g_best, g_rowmaxk, scalars) + codebook bf16 cvt.
// ---------------------------------------------------------------------------
__global__ void k_prep(const float* __restrict__ z, const float* __restrict__ cb) {
    int bid = blockIdx.x;
    if (bid < NROWS / 8) {
        int row  = bid * 8 + (threadIdx.x >> 5);
        int lane = threadIdx.x & 31;
        const float4* zp = (const float4*)(z + (size_t)row * DDIM);
        float4 a = zp[lane * 2];
        float4 b = zp[lane * 2 + 1];
        float s = a.x*a.x + a.y*a.y + a.z*a.z + a.w*a.w
                + b.x*b.x + b.y*b.y + b.z*b.z + b.w*b.w;
        #pragma unroll
        for (int o = 16; o > 0; o >>= 1) s += __shfl_xor_sync(0xffffffffu, s, o);
        if (lane == 0) {
            g_c[row] = s;
            g_best[row] = ~0ULL;
            g_rowmaxk[row] = 0u;
        }
        if (bid == 0 && threadIdx.x == 0) { g_loss = 0.0; g_done = 0u; }
    } else {
        int i = (bid - NROWS / 8) * 256 + threadIdx.x;
        float4 v = ((const float4*)cb)[i];
        g_cbb[i] = make_uint2(f2bf2(v.x, v.y), f2bf2(v.z, v.w));
    }
}

// ---------------------------------------------------------------------------
// Phase 1: persistent GEMM. 148 CTAs; work units (tile, chunk) split evenly.
// 512 threads = 16 warps as 4(row) x 4(code); warp tile 32 x 32 (R12 layout).
// z tile reloaded on tile switch (<=2 per CTA); B prefetch is tile-agnostic.
// Per-row max merged globally via fkey atomicMax. Local running-max
// admission (superset of global-threshold set; filter re-tightens).
// ---------------------------------------------------------------------------
__global__ void __launch_bounds__(512, 1)
k_phase1(const float* __restrict__ z) {
    extern __shared__ __align__(16) char sm[];
    u32 sbase = smem_u32(sm);
    u32* s_cnt = (u32*)(sm + 3 * 128 * ROWB);   // 16 per-warp counters

    int tid = threadIdx.x;
    int lane = tid & 31;
    int wid = tid >> 5;
    int wr = wid >> 2;   // 0..3 : 32-row group
    int wc = wid & 3;    // 0..3 : 32-code group
    uint2* my_slice = g_cand
        + ((size_t)blockIdx.x * NWARPS + wid) * WSLICE;

    if (tid < NWARPS) s_cnt[tid] = 0u;

    u32 ustart = (u32)(((u64)NUNITS * blockIdx.x) / GRID1);
    u32 uend   = (u32)(((u64)NUNITS * (blockIdx.x + 1)) / GRID1);

    u32 buf_u32[2] = { sbase + 128u * ROWB, sbase + 2u * 128u * ROWB };

    // prefetch first B chunk
    {
        u32 ch = ustart & (NCHUNKS - 1);
        const uint2* src = g_cbb + (size_t)ch * CHUNK * 64;
        #pragma unroll
        for (int t = 0; t < 8; t++) {
            int idx = tid + t * 512;
            int r = idx >> 5, cc = idx & 31;
            cp16(buf_u32[ustart & 1] + (u32)(r * ROWB + cc * 16),
                 src + (size_t)r * 64 + cc * 2);
        }
        CP_COMMIT();
    }
    CP_WAIT0();

    u32 a_addr = sbase + (u32)((wr * 32 + (lane & 15)) * ROWB + (lane >> 4) * 16);
    u32 b_lane = (u32)((wc * 32 + (lane & 7) + ((lane >> 4) & 1) * 8) * ROWB
                       + ((lane >> 3) & 1) * 16);

    float runmax[2][2];
    int curtile = -1;
    int rowBase = 0;

    for (u32 u = ustart; u < uend; u++) {
        int tile = (int)(u >> 6);
        u32 cbuf = buf_u32[u & 1];
        bool pf = (u + 1 < uend);

        if (tile != curtile) {
            // flush previous tile's per-row max
            if (curtile >= 0) {
                #pragma unroll
                for (int mi = 0; mi < 2; mi++)
                    #pragma unroll
                    for (int h = 0; h < 2; h++) {
                        float m = runmax[mi][h];
                        m = fmaxf(m, __shfl_xor_sync(0xffffffffu, m, 1));
                        m = fmaxf(m, __shfl_xor_sync(0xffffffffu, m, 2));
                        if ((lane & 3) == 0)
                            atomicMax(&g_rowmaxk[rowBase + wr * 32 + mi * 16
                                                 + h * 8 + (lane >> 2)],
                                      fkey(m));
                    }
            }
            curtile = tile;
            rowBase = tile * 128;
            #pragma unroll
            for (int mi = 0; mi < 2; mi++)
                #pragma unroll
                for (int h = 0; h < 2; h++)
                    runmax[mi][h] = -1e30f;
            // load z tile [128 x 256] -> bf16 smem (prior chunk's ldsm done:
            // we sync at the end of every iteration)
            const float4* src = (const float4*)(z + (size_t)rowBase * DDIM);
            #pragma unroll
            for (int t = 0; t < 16; t++) {
                int idx = tid + t * 512;
                int r = idx >> 6, c4 = idx & 63;
                float4 v = src[idx];
                *(uint2*)(sm + r * ROWB + c4 * 8) =
                    make_uint2(f2bf2(v.x, v.y), f2bf2(v.z, v.w));
            }
            __syncthreads();
        }

        if (pf) {
            u32 nb = buf_u32[(u + 1) & 1];
            u32 nch = (u + 1) & (NCHUNKS - 1);
            const uint2* src = g_cbb + (size_t)nch * CHUNK * 64;
            #pragma unroll
            for (int t = 0; t < 8; t++) {
                int idx = tid + t * 512;
                int r = idx >> 5, cc = idx & 31;
                cp16(nb + (u32)(r * ROWB + cc * 16), src + (size_t)r * 64 + cc * 2);
            }
            CP_COMMIT();
        }

        float acc[2][4][4];
        #pragma unroll
        for (int mi = 0; mi < 2; mi++)
            #pragma unroll
            for (int nj = 0; nj < 4; nj++)
                #pragma unroll
                for (int e = 0; e < 4; e++)
                    acc[mi][nj][e] = 0.0f;

        #pragma unroll
        for (int kk = 0; kk < 16; kk++) {
            u32 a[2][4];
            ldsm_x4(a[0], a_addr + kk * 32);
            ldsm_x4(a[1], a_addr + 16 * ROWB + kk * 32);
            u32 b[2][4];
            ldsm_x4(b[0], cbuf + b_lane + kk * 32);
            ldsm_x4(b[1], cbuf + b_lane + 16 * ROWB + kk * 32);
            #pragma unroll
            for (int mi = 0; mi < 2; mi++)
                #pragma unroll
                for (int njp = 0; njp < 2; njp++) {
                    mma_bf16(acc[mi][njp * 2],     a[mi], b[njp][0], b[njp][1]);
                    mma_bf16(acc[mi][njp * 2 + 1], a[mi], b[njp][2], b[njp][3]);
                }
        }

        // ---- epilogue: chunk max -> runmax -> per-warp-counter admission ----
        int c = (int)(u & (NCHUNKS - 1));
        #pragma unroll
        for (int mi = 0; mi < 2; mi++) {
            #pragma unroll
            for (int h = 0; h < 2; h++) {
                float m = -1e30f;
                #pragma unroll
                for (int nj = 0; nj < 4; nj++)
                    m = fmaxf(m, fmaxf(acc[mi][nj][h * 2], acc[mi][nj][h * 2 + 1]));
                m = fmaxf(m, __shfl_xor_sync(0xffffffffu, m, 1));
                m = fmaxf(m, __shfl_xor_sync(0xffffffffu, m, 2));
                runmax[mi][h] = fmaxf(runmax[mi][h], m);
                float thr = runmax[mi][h] - MARGIN;

                u32 msk = 0;
                #pragma unroll
                for (int nj = 0; nj < 4; nj++) {
                    if (acc[mi][nj][h * 2]     >= thr) msk |= 1u << (nj * 2);
                    if (acc[mi][nj][h * 2 + 1] >= thr) msk |= 1u << (nj * 2 + 1);
                }
                if (msk) {
                    u32 slot = atomicAdd(&s_cnt[wid], (u32)__popc(msk));
                    u32 row = (u32)(rowBase + wr * 32 + mi * 16 + h * 8
                                    + (lane >> 2));
                    #pragma unroll
                    for (int nj = 0; nj < 4; nj++) {
                        #pragma unroll
                        for (int e = 0; e < 2; e++) {
                            if (msk & (1u << (nj * 2 + e))) {
                                u32 code = (u32)(c * CHUNK + wc * 32 + nj * 8
                                                 + (lane & 3) * 2 + e);
                                if (slot < WSLICE)
                                    my_slice[slot] = make_uint2(
                                        (row << 13) | code,
                                        __float_as_uint(acc[mi][nj][h * 2 + e]));
                                slot++;
                            }
                        }
                    }
                }
            }
        }

        if (pf) CP_WAIT0();
        __syncthreads();
    }

    // final flush of last tile's row max
    if (curtile >= 0) {
        #pragma unroll
        for (int mi = 0; mi < 2; mi++)
            #pragma unroll
            for (int h = 0; h < 2; h++) {
                float m = runmax[mi][h];
                m = fmaxf(m, __shfl_xor_sync(0xffffffffu, m, 1));
                m = fmaxf(m, __shfl_xor_sync(0xffffffffu, m, 2));
                if ((lane & 3) == 0)
                    atomicMax(&g_rowmaxk[rowBase + wr * 32 + mi * 16 + h * 8
                                         + (lane >> 2)],
                              fkey(m));
            }
    }
    if (tid < NWARPS) {
        u32 n = s_cnt[tid];
        g_ccount[blockIdx.x * NWARPS + tid] = n < WSLICE ? n : WSLICE;
    }
}

// ---------------------------------------------------------------------------
// Fused filter + exact rescore: one block per warp-slice. Survivors of the
// global-rowmax threshold get the bit-exact fp32 dot (Round-2 math) and a
// packed (bits, idx) atomicMin. Order-independent -> deterministic result.
// ---------------------------------------------------------------------------
__global__ void k_rescore(const float* __restrict__ z, const float* __restrict__ cb) {
    u32 bs = blockIdx.x;                 // [0, GRID1*NWARPS)
    u32 n = g_ccount[bs];
    const uint2* slice = g_cand + (size_t)bs * WSLICE;
    for (u32 i = threadIdx.x; i < n; i += blockDim.x) {
        uint2 cd = slice[i];
        u32 row = cd.x >> 13;
        float rm = funkey(g_rowmaxk[row]);
        if (__uint_as_float(cd.y) >= rm - MARGIN) {
            u32 code = cd.x & 8191u;
            const float4* zr = (const float4*)(z + (size_t)row * DDIM);
            const float4* wr = (const float4*)(cb + (size_t)code * DDIM);
            float dot = 0.0f;
            #pragma unroll 8
            for (int q = 0; q < DDIM / 4; q++) {
                float4 a = zr[q];
                float4 b = wr[q];
                dot = __fmaf_rn(a.x, b.x, dot);
                dot = __fmaf_rn(a.y, b.y, dot);
                dot = __fmaf_rn(a.z, b.z, dot);
                dot = __fmaf_rn(a.w, b.w, dot);
            }
            float t = __fmaf_rn(-2.0f, dot, g_c[row]);
            u64 p = ((u64)__float_as_uint(t) << 32) | code;
            atomicMin(&g_best[row], p);
        }
    }
}

// ---------------------------------------------------------------------------
// k_out: gather + straight-through output + loss; LAST block finalizes
// vq_loss (fence+counter pattern; deterministic given double accumulation).
// ---------------------------------------------------------------------------
__global__ void k_out(const float* __restrict__ z, const float* __restrict__ cb,
                      float* __restrict__ out) {
    __shared__ double sred[8];
    int wid = threadIdx.x >> 5;
    int lane = threadIdx.x & 31;
    int n = blockIdx.x * 8 + wid;
    u32 idx = (u32)(g_best[n] & 0xffffffffu);
    const float4* zr = (const float4*)(z + (size_t)n * DDIM);
    const float4* qr = (const float4*)(cb + (size_t)idx * DDIM);
    float4* orow = (float4*)(out + (size_t)n * DDIM);
    double s = 0.0;
    #pragma unroll
    for (int t = 0; t < 2; t++) {
        float4 zv = zr[lane + t * 32];
        float4 qv = qr[lane + t * 32];
        float4 ov;
        ov.x = zv.x + (qv.x - zv.x);
        ov.y = zv.y + (qv.y - zv.y);
        ov.z = zv.z + (qv.z - zv.z);
        ov.w = zv.w + (qv.w - zv.w);
        orow[lane + t * 32] = ov;
        float dx = zv.x - qv.x, dy = zv.y - qv.y;
        float dz = zv.z - qv.z, dw = zv.w - qv.w;
        s += (double)(dx * dx) + (double)(dy * dy)
           + (double)(dz * dz) + (double)(dw * dw);
    }
    #pragma unroll
    for (int o = 16; o > 0; o >>= 1) s += __shfl_xor_sync(0xffffffffu, s, o);
    if (lane == 0) {
        sred[wid] = s;
        out[(size_t)NROWS * DDIM + 1 + n] = (float)idx;
    }
    __syncthreads();
    if (threadIdx.x == 0) {
        double t = 0.0;
        #pragma unroll
        for (int i = 0; i < 8; i++) t += sred[i];
        atomicAdd(&g_loss, t);
        __threadfence();
        u32 done = atomicAdd(&g_done, 1u);
        if (done == gridDim.x - 1) {
            g_done = 0u;
            double total = atomicAdd(&g_loss, 0.0);   // L2-coherent read
            float m = (float)(total / (double)((size_t)NROWS * DDIM));
            out[(size_t)NROWS * DDIM] = m + 0.25f * m;
        }
    }
}

// ---------------------------------------------------------------------------
extern "C" void kernel_launch(void* const* d_in, const int* in_sizes, int n_in,
                              void* d_out, int out_size) {
    const float* z  = (const float*)d_in[0];
    const float* cb = (const float*)d_in[1];
    if (n_in >= 2 && in_sizes[0] == KCODES * DDIM && in_sizes[1] == NROWS * DDIM) {
        z  = (const float*)d_in[1];
        cb = (const float*)d_in[0];
    }
    float* out = (float*)d_out;
    (void)out_size;

    const int smem_bytes = 3 * 128 * ROWB + 64;   // tiles + warp counters
    static int attr_done = 0;
    if (!attr_done) {
        cudaFuncSetAttribute(k_phase1, cudaFuncAttributeMaxDynamicSharedMemorySize,
                             smem_bytes);
        attr_done = 1;
    }

    k_prep<<<NROWS / 8 + KCODES * DDIM / 4 / 256, 256>>>(z, cb);
    k_phase1<<<GRID1, 512, smem_bytes>>>(z);
    k_rescore<<<GRID1 * NWARPS, 256>>>(z, cb);
    k_out<<<NROWS / 8, 256>>>(z, cb, out);
}